// round 14
// baseline (speedup 1.0000x reference)
#include <cuda_runtime.h>
#include <cuda_fp16.h>
#include <cstdint>

#define LRELU_SLOPE 0.2f
#define BN_EPS 1e-5f

constexpr int  BB  = 2;
constexpr int  NR  = 40962;
constexpr int  NH  = 4 * NR - 6;      // 163842
constexpr int  CIN = 128;
constexpr int  CO  = 64;
constexpr int  NUP = 7 * CO;          // 448
constexpr long MUP = (long)BB * NR;   // 81924
constexpr long MC  = (long)BB * NH;   // 327684
constexpr int  NPART = 512;
constexpr int  NCTA_C = (int)((MC + 127) / 128);   // 2561

__device__ __half g_hh  [(size_t)BB * NR * 7 * CO];  // up output, fp16
__device__ float  g_y   [(size_t)BB * NH * CO];      // conv1 out fp32 (stats)
__device__ __half g_x1h [(size_t)BB * NR * CIN];
__device__ __half g_x2h [(size_t)BB * NH * CO];
__device__ __half g_xuph[(size_t)BB * NH * CO];
__device__ __half g_yh  [(size_t)BB * NH * CO];
__device__ float  g_part[NPART * 128];
__device__ float  g_bn  [128];
// Fragment-packed fp16 weights: per 64-k chunk 2048 uint32 words.
__device__ float g_wupf[7 * 2 * 2048];
__device__ float g_w1f [14 * 2048];
__device__ float g_w2f [7 * 2048];

__device__ __forceinline__ uint32_t pack_h2(float lo, float hi) {
    __half2 h = __floats2half2_rn(lo, hi);
    return *reinterpret_cast<uint32_t*>(&h);
}

#define MMA_F16(d, a0, a1, a2, a3, b0, b1)                                   \
    asm volatile("mma.sync.aligned.m16n8k16.row.col.f32.f16.f16.f32 "        \
        "{%0,%1,%2,%3}, {%4,%5,%6,%7}, {%8,%9}, {%0,%1,%2,%3};"              \
        : "+f"((d)[0]), "+f"((d)[1]), "+f"((d)[2]), "+f"((d)[3])             \
        : "r"(a0), "r"(a1), "r"(a2), "r"(a3), "r"(b0), "r"(b1))

#define CP_ASYNC16(dst_u32, src)                                             \
    asm volatile("cp.async.cg.shared.global [%0], [%1], 16;"                 \
                 :: "r"(dst_u32), "l"(src) : "memory")
#define CP_COMMIT()  asm volatile("cp.async.commit_group;" ::: "memory")
#define CP_WAIT(n)   asm volatile("cp.async.wait_group %0;" :: "n"(n) : "memory")

// A smem: 128 rows x 36 uint32 words (32 half2 data + 4 pad); conflict-free.
constexpr int AS_WORDS  = 128 * 36;            // 18,432 B per buffer
constexpr int SMEM_GEMM = 2 * AS_WORDS * 4;    // 36,864 B

// ---------------------------------------------------------------------------
__global__ void round_half(const float* __restrict__ src, __half* __restrict__ dst, long nquads)
{
    long i = (long)blockIdx.x * blockDim.x + threadIdx.x;
    if (i >= nquads) return;
    float4 v = ((const float4*)src)[i];
    ((uint2*)dst)[i] = make_uint2(pack_h2(v.x, v.y), pack_h2(v.z, v.w));
}

// ---------------------------------------------------------------------------
__global__ void prep_weights(const float* __restrict__ upW,
                             const float* __restrict__ W1,
                             const float* __restrict__ W2)
{
    int f = blockIdx.x * 256 + threadIdx.x;
    if (f >= 71680) return;
    int which, c, kc, t = 0;
    if (f < 28672)      { which = 0; t = f >> 12; int in_ = f & 4095; kc = in_ >> 11; c = in_ & 2047; }
    else if (f < 57344) { which = 1; int rel = f - 28672; kc = rel >> 11; c = rel & 2047; }
    else                { which = 2; int rel = f - 57344; kc = rel >> 11; c = rel & 2047; }
    int q    = c & 3;
    int lane = (c >> 2) & 31;
    int np   = (c >> 7) & 3;
    int ks   = (c >> 9) & 3;
    int nt   = np * 2 + (q >> 1);
    int bi   = q & 1;
    int n    = nt * 8 + (lane >> 2);
    int k0   = kc * 64 + ks * 16 + (lane & 3) * 2 + bi * 8;
    float s0, s1;
    if (which == 0)      { s0 = upW[k0 * 448 + t * 64 + n]; s1 = upW[(k0 + 1) * 448 + t * 64 + n]; }
    else if (which == 1) { s0 = W1[k0 * 64 + n];            s1 = W1[(k0 + 1) * 64 + n]; }
    else                 { s0 = W2[k0 * 64 + n];            s1 = W2[(k0 + 1) * 64 + n]; }
    uint32_t u = pack_h2(s0, s1);
    if (which == 0)      g_wupf[f]          = __uint_as_float(u);
    else if (which == 1) g_w1f[f - 28672]   = __uint_as_float(u);
    else                 g_w2f[f - 57344]   = __uint_as_float(u);
}

// ---------------------------------------------------------------------------
// 32-row warp-tile fp16 GEMM. CTA = 128 threads (4 warps), (128,2) reg budget.
// ---------------------------------------------------------------------------
#define MK_VARS()                                                             \
    extern __shared__ float sm[];                                             \
    const int tid = threadIdx.x, lane = tid & 31, warp = tid >> 5;            \
    const int frow = (warp << 5) + lane;                                      \
    uint32_t as_u32 = (uint32_t)__cvta_generic_to_shared(sm);                 \
    float acc[16][4];

#define MK_ACC_ZERO()                                                         \
    _Pragma("unroll") for (int i = 0; i < 16; i++)                            \
    _Pragma("unroll") for (int j = 0; j < 4; j++) acc[i][j] = 0.f;

// Fill one 64-half row per lane: 8 x cp.async16 (128 B)
#define MK_ISSUE(buf, rowptr)                                                 \
    {                                                                         \
        uint32_t d = as_u32 + ((buf) * AS_WORDS + frow * 36) * 4;             \
        const float4* s = (const float4*)(rowptr);                            \
        _Pragma("unroll")                                                     \
        for (int i = 0; i < 8; i++) CP_ASYNC16(d + i * 16, s + i);            \
        CP_COMMIT();                                                          \
    }

#define MK_COMPUTE(buf, bchunk)                                               \
    {                                                                         \
        const uint32_t* As = (const uint32_t*)sm + (buf) * AS_WORDS;          \
        const float4* bp = (const float4*)(bchunk) + lane;                    \
        const int r0 = (warp << 5) + (lane >> 2);                             \
        const int c2 = lane & 3;                                              \
        _Pragma("unroll")                                                     \
        for (int ks = 0; ks < 4; ks++) {                                      \
            float4 bv0 = __ldg(bp + (ks * 4 + 0) * 32);                       \
            float4 bv1 = __ldg(bp + (ks * 4 + 1) * 32);                       \
            float4 bv2 = __ldg(bp + (ks * 4 + 2) * 32);                       \
            float4 bv3 = __ldg(bp + (ks * 4 + 3) * 32);                       \
            uint32_t a0 = As[ r0       * 36 + ks * 8 + c2    ];               \
            uint32_t a1 = As[(r0 + 8)  * 36 + ks * 8 + c2    ];               \
            uint32_t a2 = As[ r0       * 36 + ks * 8 + c2 + 4];               \
            uint32_t a3 = As[(r0 + 8)  * 36 + ks * 8 + c2 + 4];               \
            uint32_t a4 = As[(r0 + 16) * 36 + ks * 8 + c2    ];               \
            uint32_t a5 = As[(r0 + 24) * 36 + ks * 8 + c2    ];               \
            uint32_t a6 = As[(r0 + 16) * 36 + ks * 8 + c2 + 4];               \
            uint32_t a7 = As[(r0 + 24) * 36 + ks * 8 + c2 + 4];               \
            MMA_F16(acc[0],  a0, a1, a2, a3, __float_as_uint(bv0.x), __float_as_uint(bv0.y)); \
            MMA_F16(acc[1],  a0, a1, a2, a3, __float_as_uint(bv0.z), __float_as_uint(bv0.w)); \
            MMA_F16(acc[8],  a4, a5, a6, a7, __float_as_uint(bv0.x), __float_as_uint(bv0.y)); \
            MMA_F16(acc[9],  a4, a5, a6, a7, __float_as_uint(bv0.z), __float_as_uint(bv0.w)); \
            MMA_F16(acc[2],  a0, a1, a2, a3, __float_as_uint(bv1.x), __float_as_uint(bv1.y)); \
            MMA_F16(acc[3],  a0, a1, a2, a3, __float_as_uint(bv1.z), __float_as_uint(bv1.w)); \
            MMA_F16(acc[10], a4, a5, a6, a7, __float_as_uint(bv1.x), __float_as_uint(bv1.y)); \
            MMA_F16(acc[11], a4, a5, a6, a7, __float_as_uint(bv1.z), __float_as_uint(bv1.w)); \
            MMA_F16(acc[4],  a0, a1, a2, a3, __float_as_uint(bv2.x), __float_as_uint(bv2.y)); \
            MMA_F16(acc[5],  a0, a1, a2, a3, __float_as_uint(bv2.z), __float_as_uint(bv2.w)); \
            MMA_F16(acc[12], a4, a5, a6, a7, __float_as_uint(bv2.x), __float_as_uint(bv2.y)); \
            MMA_F16(acc[13], a4, a5, a6, a7, __float_as_uint(bv2.z), __float_as_uint(bv2.w)); \
            MMA_F16(acc[6],  a0, a1, a2, a3, __float_as_uint(bv3.x), __float_as_uint(bv3.y)); \
            MMA_F16(acc[7],  a0, a1, a2, a3, __float_as_uint(bv3.z), __float_as_uint(bv3.w)); \
            MMA_F16(acc[14], a4, a5, a6, a7, __float_as_uint(bv3.x), __float_as_uint(bv3.y)); \
            MMA_F16(acc[15], a4, a5, a6, a7, __float_as_uint(bv3.z), __float_as_uint(bv3.w)); \
        }                                                                     \
    }

#define MK_EPILOGUE(dst, ldc, Mlim, biasp)                                    \
    {                                                                         \
        long mr = rowBase + (warp << 5) + (lane >> 2);                        \
        int  cb = (lane & 3) * 2;                                             \
        _Pragma("unroll")                                                     \
        for (int nt = 0; nt < 8; nt++) {                                      \
            float bx = (biasp)[nt * 8 + cb];                                  \
            float by = (biasp)[nt * 8 + cb + 1];                              \
            if (mr < (Mlim))                                                  \
                *(float2*)((dst) + mr * (ldc) + nt * 8 + cb)                  \
                    = make_float2(acc[nt][0] + bx, acc[nt][1] + by);          \
            if (mr + 8 < (Mlim))                                              \
                *(float2*)((dst) + (mr + 8) * (ldc) + nt * 8 + cb)            \
                    = make_float2(acc[nt][2] + bx, acc[nt][3] + by);          \
            if (mr + 16 < (Mlim))                                             \
                *(float2*)((dst) + (mr + 16) * (ldc) + nt * 8 + cb)           \
                    = make_float2(acc[8 + nt][0] + bx, acc[8 + nt][1] + by);  \
            if (mr + 24 < (Mlim))                                             \
                *(float2*)((dst) + (mr + 24) * (ldc) + nt * 8 + cb)           \
                    = make_float2(acc[8 + nt][2] + bx, acc[8 + nt][3] + by);  \
        }                                                                     \
    }

// fp16 epilogue (for g_hh): packed half2 stores
#define MK_EPILOGUE_H(dst, ldc, Mlim, biasp)                                  \
    {                                                                         \
        long mr = rowBase + (warp << 5) + (lane >> 2);                        \
        int  cb = (lane & 3) * 2;                                             \
        _Pragma("unroll")                                                     \
        for (int nt = 0; nt < 8; nt++) {                                      \
            float bx = (biasp)[nt * 8 + cb];                                  \
            float by = (biasp)[nt * 8 + cb + 1];                              \
            if (mr < (Mlim))                                                  \
                *(uint32_t*)((dst) + mr * (ldc) + nt * 8 + cb)                \
                    = pack_h2(acc[nt][0] + bx, acc[nt][1] + by);              \
            if (mr + 8 < (Mlim))                                              \
                *(uint32_t*)((dst) + (mr + 8) * (ldc) + nt * 8 + cb)          \
                    = pack_h2(acc[nt][2] + bx, acc[nt][3] + by);              \
            if (mr + 16 < (Mlim))                                             \
                *(uint32_t*)((dst) + (mr + 16) * (ldc) + nt * 8 + cb)         \
                    = pack_h2(acc[8 + nt][0] + bx, acc[8 + nt][1] + by);      \
            if (mr + 24 < (Mlim))                                             \
                *(uint32_t*)((dst) + (mr + 24) * (ldc) + nt * 8 + cb)         \
                    = pack_h2(acc[8 + nt][2] + bx, acc[8 + nt][3] + by);      \
        }                                                                     \
    }

// 2-buffer, lookahead-1 pipeline (R11-proven form)
#define MK_PIPELINE(NC, ROWPTR, WPTR)                                         \
    MK_ISSUE(0, ROWPTR(0));                                                   \
    _Pragma("unroll 1")                                                       \
    for (int kc = 0; kc < (NC); kc++) {                                       \
        if (kc + 1 < (NC)) { MK_ISSUE((kc + 1) & 1, ROWPTR(kc + 1)); CP_WAIT(1); } \
        else CP_WAIT(0);                                                      \
        __syncwarp();                                                         \
        MK_COMPUTE(kc & 1, (WPTR) + kc * 2048);                               \
    }

// ---------------------------------------------------------------------------
// GEMM 1: up-projection -> g_hh (fp16). A loaded once; 7 column tiles in-CTA.
// ---------------------------------------------------------------------------
__global__ __launch_bounds__(128, 2) void gemm_up_mma(const float* __restrict__ bias)
{
    MK_VARS();
    const long rowBase = (long)blockIdx.x * 128;
    long fm = rowBase + frow; if (fm >= MUP) fm = MUP - 1;
    const __half* arow = g_x1h + fm * CIN;

    MK_ISSUE(0, arow);
    MK_ISSUE(1, arow + 64);
    CP_WAIT(0);
    __syncwarp();

    for (int t = 0; t < 7; t++) {
        MK_ACC_ZERO();
        MK_COMPUTE(0, g_wupf + (t * 2 + 0) * 2048);
        MK_COMPUTE(1, g_wupf + (t * 2 + 1) * 2048);
        MK_EPILOGUE_H(g_hh + t * 64, NUP, MUP, bias + t * 64);
    }
}

// ---------------------------------------------------------------------------
// Build x1_up: gather/mean from fp16 g_hh, write fp16
// ---------------------------------------------------------------------------
__global__ void build_xup(const int* __restrict__ topi, const int* __restrict__ downi)
{
    long idx = (long)blockIdx.x * blockDim.x + threadIdx.x;
    long total = (long)BB * NH * 16;
    if (idx >= total) return;
    long row = idx >> 4;
    int  q = (int)(idx & 15);
    int  b = (int)(row / NH);
    int  n = (int)(row - (long)b * NH);
    const __half* hb = g_hh + (size_t)b * NR * 7 * CO;
    uint2 r;
    if (n < NR) {
        int s = __ldg(topi + n);
        r = *(const uint2*)(hb + (long)s * CO + q * 4);
    } else {
        int m2 = n - NR;
        int s0 = __ldg(downi + 2 * m2);
        int s1 = __ldg(downi + 2 * m2 + 1);
        uint2 ua = *(const uint2*)(hb + (long)s0 * CO + q * 4);
        uint2 uc = *(const uint2*)(hb + (long)s1 * CO + q * 4);
        float2 a0 = __half22float2(*(__half2*)&ua.x);
        float2 a1 = __half22float2(*(__half2*)&ua.y);
        float2 c0 = __half22float2(*(__half2*)&uc.x);
        float2 c1 = __half22float2(*(__half2*)&uc.y);
        r.x = pack_h2(0.5f * (a0.x + c0.x), 0.5f * (a0.y + c0.y));
        r.y = pack_h2(0.5f * (a1.x + c1.x), 0.5f * (a1.y + c1.y));
    }
    *(uint2*)(g_xuph + row * CO + q * 4) = r;
}

// ---------------------------------------------------------------------------
__global__ __launch_bounds__(128, 2) void gemm_conv1_mma(const float* __restrict__ bias,
                                                         const int* __restrict__ neigh)
{
    MK_VARS();
    MK_ACC_ZERO();
    const long rowBase = (long)blockIdx.x * 128;
    long fm = rowBase + frow; if (fm >= MC) fm = MC - 1;
    const int  fb = (int)(fm / NH);
    const int  fn = (int)(fm - (long)fb * NH);
    const long bbase = (long)fb * NH;
    int nidx[7];
#pragma unroll
    for (int j = 0; j < 7; j++) nidx[j] = __ldg(neigh + (long)fn * 7 + j);

#define C1_ROW(kc) (((kc) & 1 ? g_x2h : g_xuph) + (bbase + nidx[(kc) >> 1]) * CO)
    MK_PIPELINE(14, C1_ROW, g_w1f);
#undef C1_ROW
    MK_EPILOGUE(g_y, CO, MC, bias);
}

// ---------------------------------------------------------------------------
__global__ __launch_bounds__(128, 2) void gemm_conv2_mma(const float* __restrict__ bias,
                                                         const int* __restrict__ neigh,
                                                         float* __restrict__ out)
{
    MK_VARS();
    MK_ACC_ZERO();
    const long rowBase = (long)blockIdx.x * 128;
    long fm = rowBase + frow; if (fm >= MC) fm = MC - 1;
    const int  fb = (int)(fm / NH);
    const int  fn = (int)(fm - (long)fb * NH);
    const long bbase = (long)fb * NH;
    int nidx[7];
#pragma unroll
    for (int j = 0; j < 7; j++) nidx[j] = __ldg(neigh + (long)fn * 7 + j);

#define C2_ROW(kc) (g_yh + (bbase + nidx[kc]) * CO)
    MK_PIPELINE(7, C2_ROW, g_w2f);
#undef C2_ROW
    MK_EPILOGUE(out, CO, MC, bias);
}

// ---------------------------------------------------------------------------
__global__ __launch_bounds__(256) void reduce_stats(const float* __restrict__ data, long Mrows)
{
    __shared__ float4 sh_s [16][16];
    __shared__ float4 sh_ss[16][16];
    int q  = threadIdx.x & 15;
    int rg = threadIdx.x >> 4;
    float4 s  = make_float4(0.f, 0.f, 0.f, 0.f);
    float4 ss = make_float4(0.f, 0.f, 0.f, 0.f);
    for (long r = (long)blockIdx.x * 16 + rg; r < Mrows; r += (long)gridDim.x * 16) {
        float4 v = *(const float4*)(data + r * 64 + q * 4);
        s.x += v.x; s.y += v.y; s.z += v.z; s.w += v.w;
        ss.x = fmaf(v.x, v.x, ss.x); ss.y = fmaf(v.y, v.y, ss.y);
        ss.z = fmaf(v.z, v.z, ss.z); ss.w = fmaf(v.w, v.w, ss.w);
    }
    sh_s[rg][q] = s; sh_ss[rg][q] = ss;
    __syncthreads();
#pragma unroll
    for (int stride = 8; stride >= 1; stride >>= 1) {
        if (rg < stride) {
            float4 a = sh_s[rg][q], b = sh_s[rg + stride][q];
            a.x += b.x; a.y += b.y; a.z += b.z; a.w += b.w;
            sh_s[rg][q] = a;
            float4 c = sh_ss[rg][q], d = sh_ss[rg + stride][q];
            c.x += d.x; c.y += d.y; c.z += d.z; c.w += d.w;
            sh_ss[rg][q] = c;
        }
        __syncthreads();
    }
    if (rg == 0) {
        *(float4*)(g_part + blockIdx.x * 128 + q * 4)      = sh_s[0][q];
        *(float4*)(g_part + blockIdx.x * 128 + 64 + q * 4) = sh_ss[0][q];
    }
}

__global__ void bn_finalize(const float* __restrict__ gamma,
                            const float* __restrict__ beta, float invM)
{
    int c = threadIdx.x;
    float s = 0.f, ss = 0.f;
    for (int p = 0; p < NPART; p++) {
        s  += g_part[p * 128 + c];
        ss += g_part[p * 128 + 64 + c];
    }
    float mean = s * invM;
    float var  = fmaf(-mean, mean, ss * invM);
    float sc   = gamma[c] * rsqrtf(var + BN_EPS);
    g_bn[c]      = sc;
    g_bn[64 + c] = beta[c] - mean * sc;
}

__global__ void apply_bn1_half()
{
    long idx = (long)blockIdx.x * blockDim.x + threadIdx.x;
    if (idx >= MC * 16) return;
    int q = (int)(idx & 15);
    float4 v  = ((float4*)g_y)[idx];
    float4 sc = *(const float4*)&g_bn[q * 4];
    float4 sh = *(const float4*)&g_bn[64 + q * 4];
    v.x = fmaf(v.x, sc.x, sh.x); v.x = v.x >= 0.f ? v.x : LRELU_SLOPE * v.x;
    v.y = fmaf(v.y, sc.y, sh.y); v.y = v.y >= 0.f ? v.y : LRELU_SLOPE * v.y;
    v.z = fmaf(v.z, sc.z, sh.z); v.z = v.z >= 0.f ? v.z : LRELU_SLOPE * v.z;
    v.w = fmaf(v.w, sc.w, sh.w); v.w = v.w >= 0.f ? v.w : LRELU_SLOPE * v.w;
    ((uint2*)g_yh)[idx] = make_uint2(pack_h2(v.x, v.y), pack_h2(v.z, v.w));
}

__global__ void apply_bn(float* __restrict__ out)
{
    long idx = (long)blockIdx.x * blockDim.x + threadIdx.x;
    if (idx >= MC * 16) return;
    int q = (int)(idx & 15);
    float4 v  = ((float4*)out)[idx];
    float4 sc = *(const float4*)&g_bn[q * 4];
    float4 sh = *(const float4*)&g_bn[64 + q * 4];
    v.x = fmaf(v.x, sc.x, sh.x); v.x = v.x >= 0.f ? v.x : LRELU_SLOPE * v.x;
    v.y = fmaf(v.y, sc.y, sh.y); v.y = v.y >= 0.f ? v.y : LRELU_SLOPE * v.y;
    v.z = fmaf(v.z, sc.z, sh.z); v.z = v.z >= 0.f ? v.z : LRELU_SLOPE * v.z;
    v.w = fmaf(v.w, sc.w, sh.w); v.w = v.w >= 0.f ? v.w : LRELU_SLOPE * v.w;
    ((float4*)out)[idx] = v;
}

// ---------------------------------------------------------------------------
extern "C" void kernel_launch(void* const* d_in, const int* in_sizes, int n_in,
                              void* d_out, int out_size)
{
    const float* x1    = (const float*)d_in[0];
    const float* x2    = (const float*)d_in[1];
    const int*   neigh = (const int*)  d_in[2];
    const int*   topi  = (const int*)  d_in[3];
    const int*   downi = (const int*)  d_in[4];
    const float* upW   = (const float*)d_in[5];
    const float* upb   = (const float*)d_in[6];
    const float* W1    = (const float*)d_in[7];
    const float* b1    = (const float*)d_in[8];
    const float* g1    = (const float*)d_in[9];
    const float* be1   = (const float*)d_in[10];
    const float* W2    = (const float*)d_in[11];
    const float* b2    = (const float*)d_in[12];
    const float* g2    = (const float*)d_in[13];
    const float* be2   = (const float*)d_in[14];
    float* out = (float*)d_out;

    cudaFuncSetAttribute(gemm_up_mma,    cudaFuncAttributeMaxDynamicSharedMemorySize, SMEM_GEMM);
    cudaFuncSetAttribute(gemm_conv1_mma, cudaFuncAttributeMaxDynamicSharedMemorySize, SMEM_GEMM);
    cudaFuncSetAttribute(gemm_conv2_mma, cudaFuncAttributeMaxDynamicSharedMemorySize, SMEM_GEMM);

    void *yp = nullptr, *x1h = nullptr, *x2h = nullptr;
    cudaGetSymbolAddress(&yp, g_y);
    cudaGetSymbolAddress(&x1h, g_x1h);
    cudaGetSymbolAddress(&x2h, g_x2h);

    const int blkUp = (int)((MUP + 127) / 128);
    const long quads   = (long)BB * NH * 16;
    const int ewBlocks = (int)((quads + 255) / 256);
    const int pwBlocks = (71680 + 255) / 256;
    const long q1 = MUP * CIN / 4, q2 = MC * CO / 4;

    prep_weights  <<<pwBlocks, 256>>>(upW, W1, W2);
    round_half    <<<(int)((q1 + 255) / 256), 256>>>(x1, (__half*)x1h, q1);
    round_half    <<<(int)((q2 + 255) / 256), 256>>>(x2, (__half*)x2h, q2);
    gemm_up_mma   <<<blkUp, 128, SMEM_GEMM>>>(upb);
    build_xup     <<<ewBlocks, 256>>>(topi, downi);
    gemm_conv1_mma<<<NCTA_C, 128, SMEM_GEMM>>>(b1, neigh);
    reduce_stats  <<<NPART, 256>>>((const float*)yp, MC);
    bn_finalize   <<<1, 64>>>(g1, be1, 1.0f / (float)MC);
    apply_bn1_half<<<ewBlocks, 256>>>();
    gemm_conv2_mma<<<NCTA_C, 128, SMEM_GEMM>>>(b2, neigh, out);
    reduce_stats  <<<NPART, 256>>>(out, MC);
    bn_finalize   <<<1, 64>>>(g2, be2, 1.0f / (float)MC);
    apply_bn      <<<ewBlocks, 256>>>(out);
}

// round 15
// speedup vs baseline: 1.4861x; 1.4861x over previous
#include <cuda_runtime.h>
#include <cuda_fp16.h>
#include <cstdint>

#define LRELU_SLOPE 0.2f
#define BN_EPS 1e-5f

constexpr int  BB  = 2;
constexpr int  NR  = 40962;
constexpr int  NH  = 4 * NR - 6;      // 163842
constexpr int  CIN = 128;
constexpr int  CO  = 64;
constexpr int  NUP = 7 * CO;          // 448
constexpr long MUP = (long)BB * NR;   // 81924
constexpr long MC  = (long)BB * NH;   // 327684
constexpr int  NPART = 512;
constexpr int  NCTA_C = (int)((MC + 127) / 128);   // 2561

__device__ __half g_hh  [(size_t)BB * NR * 7 * CO];  // up output, fp16
__device__ float  g_y   [(size_t)BB * NH * CO];      // conv1 out fp32 (stats)
__device__ __half g_x1h [(size_t)BB * NR * CIN];
__device__ __half g_x2h [(size_t)BB * NH * CO];
__device__ __half g_xuph[(size_t)BB * NH * CO];
__device__ __half g_yh  [(size_t)BB * NH * CO];
__device__ float  g_part[NPART * 128];
__device__ float  g_bn  [128];
// Fragment-packed fp16 weights: per 64-k chunk 2048 uint32 words.
__device__ float g_wupf[7 * 2 * 2048];
__device__ float g_w1f [14 * 2048];
__device__ float g_w2f [7 * 2048];

__device__ __forceinline__ uint32_t pack_h2(float lo, float hi) {
    __half2 h = __floats2half2_rn(lo, hi);
    return *reinterpret_cast<uint32_t*>(&h);
}

#define MMA_F16(d, a0, a1, a2, a3, b0, b1)                                   \
    asm volatile("mma.sync.aligned.m16n8k16.row.col.f32.f16.f16.f32 "        \
        "{%0,%1,%2,%3}, {%4,%5,%6,%7}, {%8,%9}, {%0,%1,%2,%3};"              \
        : "+f"((d)[0]), "+f"((d)[1]), "+f"((d)[2]), "+f"((d)[3])             \
        : "r"(a0), "r"(a1), "r"(a2), "r"(a3), "r"(b0), "r"(b1))

#define CP_ASYNC16(dst_u32, src)                                             \
    asm volatile("cp.async.cg.shared.global [%0], [%1], 16;"                 \
                 :: "r"(dst_u32), "l"(src) : "memory")
#define CP_COMMIT()  asm volatile("cp.async.commit_group;" ::: "memory")
#define CP_WAIT(n)   asm volatile("cp.async.wait_group %0;" :: "n"(n) : "memory")

// A smem: 128 rows x 36 uint32 words (32 half2 data + 4 pad); conflict-free.
constexpr int AS_WORDS  = 128 * 36;            // 18,432 B per buffer
constexpr int SMEM_GEMM = 2 * AS_WORDS * 4;    // 36,864 B

// ---------------------------------------------------------------------------
__global__ void round_half(const float* __restrict__ src, __half* __restrict__ dst, long nquads)
{
    long i = (long)blockIdx.x * blockDim.x + threadIdx.x;
    if (i >= nquads) return;
    float4 v = ((const float4*)src)[i];
    ((uint2*)dst)[i] = make_uint2(pack_h2(v.x, v.y), pack_h2(v.z, v.w));
}

// ---------------------------------------------------------------------------
__global__ void prep_weights(const float* __restrict__ upW,
                             const float* __restrict__ W1,
                             const float* __restrict__ W2)
{
    int f = blockIdx.x * 256 + threadIdx.x;
    if (f >= 71680) return;
    int which, c, kc, t = 0;
    if (f < 28672)      { which = 0; t = f >> 12; int in_ = f & 4095; kc = in_ >> 11; c = in_ & 2047; }
    else if (f < 57344) { which = 1; int rel = f - 28672; kc = rel >> 11; c = rel & 2047; }
    else                { which = 2; int rel = f - 57344; kc = rel >> 11; c = rel & 2047; }
    int q    = c & 3;
    int lane = (c >> 2) & 31;
    int np   = (c >> 7) & 3;
    int ks   = (c >> 9) & 3;
    int nt   = np * 2 + (q >> 1);
    int bi   = q & 1;
    int n    = nt * 8 + (lane >> 2);
    int k0   = kc * 64 + ks * 16 + (lane & 3) * 2 + bi * 8;
    float s0, s1;
    if (which == 0)      { s0 = upW[k0 * 448 + t * 64 + n]; s1 = upW[(k0 + 1) * 448 + t * 64 + n]; }
    else if (which == 1) { s0 = W1[k0 * 64 + n];            s1 = W1[(k0 + 1) * 64 + n]; }
    else                 { s0 = W2[k0 * 64 + n];            s1 = W2[(k0 + 1) * 64 + n]; }
    uint32_t u = pack_h2(s0, s1);
    if (which == 0)      g_wupf[f]          = __uint_as_float(u);
    else if (which == 1) g_w1f[f - 28672]   = __uint_as_float(u);
    else                 g_w2f[f - 57344]   = __uint_as_float(u);
}

// ---------------------------------------------------------------------------
// 32-row warp-tile fp16 GEMM. CTA = 128 threads (4 warps), (128,3).  [R11]
// ---------------------------------------------------------------------------
#define MK_VARS()                                                             \
    extern __shared__ float sm[];                                             \
    const int tid = threadIdx.x, lane = tid & 31, warp = tid >> 5;            \
    const int frow = (warp << 5) + lane;                                      \
    uint32_t as_u32 = (uint32_t)__cvta_generic_to_shared(sm);                 \
    float acc[16][4];

#define MK_ACC_ZERO()                                                         \
    _Pragma("unroll") for (int i = 0; i < 16; i++)                            \
    _Pragma("unroll") for (int j = 0; j < 4; j++) acc[i][j] = 0.f;

#define MK_ISSUE(buf, rowptr)                                                 \
    {                                                                         \
        uint32_t d = as_u32 + ((buf) * AS_WORDS + frow * 36) * 4;             \
        const float4* s = (const float4*)(rowptr);                            \
        _Pragma("unroll")                                                     \
        for (int i = 0; i < 8; i++) CP_ASYNC16(d + i * 16, s + i);            \
        CP_COMMIT();                                                          \
    }

#define MK_COMPUTE(buf, bchunk)                                               \
    {                                                                         \
        const uint32_t* As = (const uint32_t*)sm + (buf) * AS_WORDS;          \
        const float4* bp = (const float4*)(bchunk) + lane;                    \
        const int r0 = (warp << 5) + (lane >> 2);                             \
        const int c2 = lane & 3;                                              \
        _Pragma("unroll")                                                     \
        for (int ks = 0; ks < 4; ks++) {                                      \
            float4 bv0 = __ldg(bp + (ks * 4 + 0) * 32);                       \
            float4 bv1 = __ldg(bp + (ks * 4 + 1) * 32);                       \
            float4 bv2 = __ldg(bp + (ks * 4 + 2) * 32);                       \
            float4 bv3 = __ldg(bp + (ks * 4 + 3) * 32);                       \
            uint32_t a0 = As[ r0       * 36 + ks * 8 + c2    ];               \
            uint32_t a1 = As[(r0 + 8)  * 36 + ks * 8 + c2    ];               \
            uint32_t a2 = As[ r0       * 36 + ks * 8 + c2 + 4];               \
            uint32_t a3 = As[(r0 + 8)  * 36 + ks * 8 + c2 + 4];               \
            uint32_t a4 = As[(r0 + 16) * 36 + ks * 8 + c2    ];               \
            uint32_t a5 = As[(r0 + 24) * 36 + ks * 8 + c2    ];               \
            uint32_t a6 = As[(r0 + 16) * 36 + ks * 8 + c2 + 4];               \
            uint32_t a7 = As[(r0 + 24) * 36 + ks * 8 + c2 + 4];               \
            MMA_F16(acc[0],  a0, a1, a2, a3, __float_as_uint(bv0.x), __float_as_uint(bv0.y)); \
            MMA_F16(acc[1],  a0, a1, a2, a3, __float_as_uint(bv0.z), __float_as_uint(bv0.w)); \
            MMA_F16(acc[8],  a4, a5, a6, a7, __float_as_uint(bv0.x), __float_as_uint(bv0.y)); \
            MMA_F16(acc[9],  a4, a5, a6, a7, __float_as_uint(bv0.z), __float_as_uint(bv0.w)); \
            MMA_F16(acc[2],  a0, a1, a2, a3, __float_as_uint(bv1.x), __float_as_uint(bv1.y)); \
            MMA_F16(acc[3],  a0, a1, a2, a3, __float_as_uint(bv1.z), __float_as_uint(bv1.w)); \
            MMA_F16(acc[10], a4, a5, a6, a7, __float_as_uint(bv1.x), __float_as_uint(bv1.y)); \
            MMA_F16(acc[11], a4, a5, a6, a7, __float_as_uint(bv1.z), __float_as_uint(bv1.w)); \
            MMA_F16(acc[4],  a0, a1, a2, a3, __float_as_uint(bv2.x), __float_as_uint(bv2.y)); \
            MMA_F16(acc[5],  a0, a1, a2, a3, __float_as_uint(bv2.z), __float_as_uint(bv2.w)); \
            MMA_F16(acc[12], a4, a5, a6, a7, __float_as_uint(bv2.x), __float_as_uint(bv2.y)); \
            MMA_F16(acc[13], a4, a5, a6, a7, __float_as_uint(bv2.z), __float_as_uint(bv2.w)); \
            MMA_F16(acc[6],  a0, a1, a2, a3, __float_as_uint(bv3.x), __float_as_uint(bv3.y)); \
            MMA_F16(acc[7],  a0, a1, a2, a3, __float_as_uint(bv3.z), __float_as_uint(bv3.w)); \
            MMA_F16(acc[14], a4, a5, a6, a7, __float_as_uint(bv3.x), __float_as_uint(bv3.y)); \
            MMA_F16(acc[15], a4, a5, a6, a7, __float_as_uint(bv3.z), __float_as_uint(bv3.w)); \
        }                                                                     \
    }

#define MK_EPILOGUE(dst, ldc, Mlim, biasp)                                    \
    {                                                                         \
        long mr = rowBase + (warp << 5) + (lane >> 2);                        \
        int  cb = (lane & 3) * 2;                                             \
        _Pragma("unroll")                                                     \
        for (int nt = 0; nt < 8; nt++) {                                      \
            float bx = (biasp)[nt * 8 + cb];                                  \
            float by = (biasp)[nt * 8 + cb + 1];                              \
            if (mr < (Mlim))                                                  \
                *(float2*)((dst) + mr * (ldc) + nt * 8 + cb)                  \
                    = make_float2(acc[nt][0] + bx, acc[nt][1] + by);          \
            if (mr + 8 < (Mlim))                                              \
                *(float2*)((dst) + (mr + 8) * (ldc) + nt * 8 + cb)            \
                    = make_float2(acc[nt][2] + bx, acc[nt][3] + by);          \
            if (mr + 16 < (Mlim))                                             \
                *(float2*)((dst) + (mr + 16) * (ldc) + nt * 8 + cb)           \
                    = make_float2(acc[8 + nt][0] + bx, acc[8 + nt][1] + by);  \
            if (mr + 24 < (Mlim))                                             \
                *(float2*)((dst) + (mr + 24) * (ldc) + nt * 8 + cb)           \
                    = make_float2(acc[8 + nt][2] + bx, acc[8 + nt][3] + by);  \
        }                                                                     \
    }

// fp16 epilogue (for g_hh): packed half2 stores
#define MK_EPILOGUE_H(dst, ldc, Mlim, biasp)                                  \
    {                                                                         \
        long mr = rowBase + (warp << 5) + (lane >> 2);                        \
        int  cb = (lane & 3) * 2;                                             \
        _Pragma("unroll")                                                     \
        for (int nt = 0; nt < 8; nt++) {                                      \
            float bx = (biasp)[nt * 8 + cb];                                  \
            float by = (biasp)[nt * 8 + cb + 1];                              \
            if (mr < (Mlim))                                                  \
                *(uint32_t*)((dst) + mr * (ldc) + nt * 8 + cb)                \
                    = pack_h2(acc[nt][0] + bx, acc[nt][1] + by);              \
            if (mr + 8 < (Mlim))                                              \
                *(uint32_t*)((dst) + (mr + 8) * (ldc) + nt * 8 + cb)          \
                    = pack_h2(acc[nt][2] + bx, acc[nt][3] + by);              \
            if (mr + 16 < (Mlim))                                             \
                *(uint32_t*)((dst) + (mr + 16) * (ldc) + nt * 8 + cb)         \
                    = pack_h2(acc[8 + nt][0] + bx, acc[8 + nt][1] + by);      \
            if (mr + 24 < (Mlim))                                             \
                *(uint32_t*)((dst) + (mr + 24) * (ldc) + nt * 8 + cb)         \
                    = pack_h2(acc[8 + nt][2] + bx, acc[8 + nt][3] + by);      \
        }                                                                     \
    }

// 2-buffer, lookahead-1 pipeline (R11 form)
#define MK_PIPELINE(NC, ROWPTR, WPTR)                                         \
    MK_ISSUE(0, ROWPTR(0));                                                   \
    _Pragma("unroll 1")                                                       \
    for (int kc = 0; kc < (NC); kc++) {                                       \
        if (kc + 1 < (NC)) { MK_ISSUE((kc + 1) & 1, ROWPTR(kc + 1)); CP_WAIT(1); } \
        else CP_WAIT(0);                                                      \
        __syncwarp();                                                         \
        MK_COMPUTE(kc & 1, (WPTR) + kc * 2048);                               \
    }

// ---------------------------------------------------------------------------
// GEMM 1: up-projection -> g_hh (fp16). A loaded once; 7 column tiles in-CTA.
// ---------------------------------------------------------------------------
__global__ __launch_bounds__(128, 3) void gemm_up_mma(const float* __restrict__ bias)
{
    MK_VARS();
    const long rowBase = (long)blockIdx.x * 128;
    long fm = rowBase + frow; if (fm >= MUP) fm = MUP - 1;
    const __half* arow = g_x1h + fm * CIN;

    MK_ISSUE(0, arow);
    MK_ISSUE(1, arow + 64);
    CP_WAIT(0);
    __syncwarp();

    for (int t = 0; t < 7; t++) {
        MK_ACC_ZERO();
        MK_COMPUTE(0, g_wupf + (t * 2 + 0) * 2048);
        MK_COMPUTE(1, g_wupf + (t * 2 + 1) * 2048);
        MK_EPILOGUE_H(g_hh + t * 64, NUP, MUP, bias + t * 64);
    }
}

// ---------------------------------------------------------------------------
// Build x1_up: gather/mean from fp16 g_hh, write fp16
// ---------------------------------------------------------------------------
__global__ void build_xup(const int* __restrict__ topi, const int* __restrict__ downi)
{
    long idx = (long)blockIdx.x * blockDim.x + threadIdx.x;
    long total = (long)BB * NH * 16;
    if (idx >= total) return;
    long row = idx >> 4;
    int  q = (int)(idx & 15);
    int  b = (int)(row / NH);
    int  n = (int)(row - (long)b * NH);
    const __half* hb = g_hh + (size_t)b * NR * 7 * CO;
    uint2 r;
    if (n < NR) {
        int s = __ldg(topi + n);
        r = *(const uint2*)(hb + (long)s * CO + q * 4);
    } else {
        int m2 = n - NR;
        int s0 = __ldg(downi + 2 * m2);
        int s1 = __ldg(downi + 2 * m2 + 1);
        uint2 ua = *(const uint2*)(hb + (long)s0 * CO + q * 4);
        uint2 uc = *(const uint2*)(hb + (long)s1 * CO + q * 4);
        float2 a0 = __half22float2(*(__half2*)&ua.x);
        float2 a1 = __half22float2(*(__half2*)&ua.y);
        float2 c0 = __half22float2(*(__half2*)&uc.x);
        float2 c1 = __half22float2(*(__half2*)&uc.y);
        r.x = pack_h2(0.5f * (a0.x + c0.x), 0.5f * (a0.y + c0.y));
        r.y = pack_h2(0.5f * (a1.x + c1.x), 0.5f * (a1.y + c1.y));
    }
    *(uint2*)(g_xuph + row * CO + q * 4) = r;
}

// ---------------------------------------------------------------------------
__global__ __launch_bounds__(128, 3) void gemm_conv1_mma(const float* __restrict__ bias,
                                                         const int* __restrict__ neigh)
{
    MK_VARS();
    MK_ACC_ZERO();
    const long rowBase = (long)blockIdx.x * 128;
    long fm = rowBase + frow; if (fm >= MC) fm = MC - 1;
    const int  fb = (int)(fm / NH);
    const int  fn = (int)(fm - (long)fb * NH);
    const long bbase = (long)fb * NH;
    int nidx[7];
#pragma unroll
    for (int j = 0; j < 7; j++) nidx[j] = __ldg(neigh + (long)fn * 7 + j);

#define C1_ROW(kc) (((kc) & 1 ? g_x2h : g_xuph) + (bbase + nidx[(kc) >> 1]) * CO)
    MK_PIPELINE(14, C1_ROW, g_w1f);
#undef C1_ROW
    MK_EPILOGUE(g_y, CO, MC, bias);
}

// ---------------------------------------------------------------------------
__global__ __launch_bounds__(128, 3) void gemm_conv2_mma(const float* __restrict__ bias,
                                                         const int* __restrict__ neigh,
                                                         float* __restrict__ out)
{
    MK_VARS();
    MK_ACC_ZERO();
    const long rowBase = (long)blockIdx.x * 128;
    long fm = rowBase + frow; if (fm >= MC) fm = MC - 1;
    const int  fb = (int)(fm / NH);
    const int  fn = (int)(fm - (long)fb * NH);
    const long bbase = (long)fb * NH;
    int nidx[7];
#pragma unroll
    for (int j = 0; j < 7; j++) nidx[j] = __ldg(neigh + (long)fn * 7 + j);

#define C2_ROW(kc) (g_yh + (bbase + nidx[kc]) * CO)
    MK_PIPELINE(7, C2_ROW, g_w2f);
#undef C2_ROW
    MK_EPILOGUE(out, CO, MC, bias);
}

// ---------------------------------------------------------------------------
__global__ __launch_bounds__(256) void reduce_stats(const float* __restrict__ data, long Mrows)
{
    __shared__ float4 sh_s [16][16];
    __shared__ float4 sh_ss[16][16];
    int q  = threadIdx.x & 15;
    int rg = threadIdx.x >> 4;
    float4 s  = make_float4(0.f, 0.f, 0.f, 0.f);
    float4 ss = make_float4(0.f, 0.f, 0.f, 0.f);
    for (long r = (long)blockIdx.x * 16 + rg; r < Mrows; r += (long)gridDim.x * 16) {
        float4 v = *(const float4*)(data + r * 64 + q * 4);
        s.x += v.x; s.y += v.y; s.z += v.z; s.w += v.w;
        ss.x = fmaf(v.x, v.x, ss.x); ss.y = fmaf(v.y, v.y, ss.y);
        ss.z = fmaf(v.z, v.z, ss.z); ss.w = fmaf(v.w, v.w, ss.w);
    }
    sh_s[rg][q] = s; sh_ss[rg][q] = ss;
    __syncthreads();
#pragma unroll
    for (int stride = 8; stride >= 1; stride >>= 1) {
        if (rg < stride) {
            float4 a = sh_s[rg][q], b = sh_s[rg + stride][q];
            a.x += b.x; a.y += b.y; a.z += b.z; a.w += b.w;
            sh_s[rg][q] = a;
            float4 c = sh_ss[rg][q], d = sh_ss[rg + stride][q];
            c.x += d.x; c.y += d.y; c.z += d.z; c.w += d.w;
            sh_ss[rg][q] = c;
        }
        __syncthreads();
    }
    if (rg == 0) {
        *(float4*)(g_part + blockIdx.x * 128 + q * 4)      = sh_s[0][q];
        *(float4*)(g_part + blockIdx.x * 128 + 64 + q * 4) = sh_ss[0][q];
    }
}

__global__ void bn_finalize(const float* __restrict__ gamma,
                            const float* __restrict__ beta, float invM)
{
    int c = threadIdx.x;
    float s = 0.f, ss = 0.f;
    for (int p = 0; p < NPART; p++) {
        s  += g_part[p * 128 + c];
        ss += g_part[p * 128 + 64 + c];
    }
    float mean = s * invM;
    float var  = fmaf(-mean, mean, ss * invM);
    float sc   = gamma[c] * rsqrtf(var + BN_EPS);
    g_bn[c]      = sc;
    g_bn[64 + c] = beta[c] - mean * sc;
}

__global__ void apply_bn1_half()
{
    long idx = (long)blockIdx.x * blockDim.x + threadIdx.x;
    if (idx >= MC * 16) return;
    int q = (int)(idx & 15);
    float4 v  = ((float4*)g_y)[idx];
    float4 sc = *(const float4*)&g_bn[q * 4];
    float4 sh = *(const float4*)&g_bn[64 + q * 4];
    v.x = fmaf(v.x, sc.x, sh.x); v.x = v.x >= 0.f ? v.x : LRELU_SLOPE * v.x;
    v.y = fmaf(v.y, sc.y, sh.y); v.y = v.y >= 0.f ? v.y : LRELU_SLOPE * v.y;
    v.z = fmaf(v.z, sc.z, sh.z); v.z = v.z >= 0.f ? v.z : LRELU_SLOPE * v.z;
    v.w = fmaf(v.w, sc.w, sh.w); v.w = v.w >= 0.f ? v.w : LRELU_SLOPE * v.w;
    ((uint2*)g_yh)[idx] = make_uint2(pack_h2(v.x, v.y), pack_h2(v.z, v.w));
}

__global__ void apply_bn(float* __restrict__ out)
{
    long idx = (long)blockIdx.x * blockDim.x + threadIdx.x;
    if (idx >= MC * 16) return;
    int q = (int)(idx & 15);
    float4 v  = ((float4*)out)[idx];
    float4 sc = *(const float4*)&g_bn[q * 4];
    float4 sh = *(const float4*)&g_bn[64 + q * 4];
    v.x = fmaf(v.x, sc.x, sh.x); v.x = v.x >= 0.f ? v.x : LRELU_SLOPE * v.x;
    v.y = fmaf(v.y, sc.y, sh.y); v.y = v.y >= 0.f ? v.y : LRELU_SLOPE * v.y;
    v.z = fmaf(v.z, sc.z, sh.z); v.z = v.z >= 0.f ? v.z : LRELU_SLOPE * v.z;
    v.w = fmaf(v.w, sc.w, sh.w); v.w = v.w >= 0.f ? v.w : LRELU_SLOPE * v.w;
    ((float4*)out)[idx] = v;
}

// ---------------------------------------------------------------------------
extern "C" void kernel_launch(void* const* d_in, const int* in_sizes, int n_in,
                              void* d_out, int out_size)
{
    const float* x1    = (const float*)d_in[0];
    const float* x2    = (const float*)d_in[1];
    const int*   neigh = (const int*)  d_in[2];
    const int*   topi  = (const int*)  d_in[3];
    const int*   downi = (const int*)  d_in[4];
    const float* upW   = (const float*)d_in[5];
    const float* upb   = (const float*)d_in[6];
    const float* W1    = (const float*)d_in[7];
    const float* b1    = (const float*)d_in[8];
    const float* g1    = (const float*)d_in[9];
    const float* be1   = (const float*)d_in[10];
    const float* W2    = (const float*)d_in[11];
    const float* b2    = (const float*)d_in[12];
    const float* g2    = (const float*)d_in[13];
    const float* be2   = (const float*)d_in[14];
    float* out = (float*)d_out;

    cudaFuncSetAttribute(gemm_up_mma,    cudaFuncAttributeMaxDynamicSharedMemorySize, SMEM_GEMM);
    cudaFuncSetAttribute(gemm_conv1_mma, cudaFuncAttributeMaxDynamicSharedMemorySize, SMEM_GEMM);
    cudaFuncSetAttribute(gemm_conv2_mma, cudaFuncAttributeMaxDynamicSharedMemorySize, SMEM_GEMM);

    void *yp = nullptr, *x1h = nullptr, *x2h = nullptr;
    cudaGetSymbolAddress(&yp, g_y);
    cudaGetSymbolAddress(&x1h, g_x1h);
    cudaGetSymbolAddress(&x2h, g_x2h);

    const int blkUp = (int)((MUP + 127) / 128);
    const long quads   = (long)BB * NH * 16;
    const int ewBlocks = (int)((quads + 255) / 256);
    const int pwBlocks = (71680 + 255) / 256;
    const long q1 = MUP * CIN / 4, q2 = MC * CO / 4;

    prep_weights  <<<pwBlocks, 256>>>(upW, W1, W2);
    round_half    <<<(int)((q1 + 255) / 256), 256>>>(x1, (__half*)x1h, q1);
    round_half    <<<(int)((q2 + 255) / 256), 256>>>(x2, (__half*)x2h, q2);
    gemm_up_mma   <<<blkUp, 128, SMEM_GEMM>>>(upb);
    build_xup     <<<ewBlocks, 256>>>(topi, downi);
    gemm_conv1_mma<<<NCTA_C, 128, SMEM_GEMM>>>(b1, neigh);
    reduce_stats  <<<NPART, 256>>>((const float*)yp, MC);
    bn_finalize   <<<1, 64>>>(g1, be1, 1.0f / (float)MC);
    apply_bn1_half<<<ewBlocks, 256>>>();
    gemm_conv2_mma<<<NCTA_C, 128, SMEM_GEMM>>>(b2, neigh, out);
    reduce_stats  <<<NPART, 256>>>(out, MC);
    bn_finalize   <<<1, 64>>>(g2, be2, 1.0f / (float)MC);
    apply_bn      <<<ewBlocks, 256>>>(out);
}

// round 16
// speedup vs baseline: 1.5578x; 1.0483x over previous
#include <cuda_runtime.h>
#include <cuda_fp16.h>
#include <cstdint>

#define LRELU_SLOPE 0.2f
#define BN_EPS 1e-5f

constexpr int  BB  = 2;
constexpr int  NR  = 40962;
constexpr int  NH  = 4 * NR - 6;      // 163842
constexpr int  CIN = 128;
constexpr int  CO  = 64;
constexpr int  NUP = 7 * CO;          // 448
constexpr long MUP = (long)BB * NR;   // 81924
constexpr long MC  = (long)BB * NH;   // 327684
constexpr int  NPART = 512;
constexpr int  NCTA_C = (int)((MC + 127) / 128);   // 2561

__device__ __half g_hh  [(size_t)BB * NR * 7 * CO];  // up output fp16; reused for conv2 raw out
__device__ __half g_x1h [(size_t)BB * NR * CIN];
__device__ __half g_x2h [(size_t)BB * NH * CO];
__device__ __half g_xuph[(size_t)BB * NH * CO];
__device__ __half g_yh  [(size_t)BB * NH * CO];      // conv1 raw out -> bn1 in place
__device__ float  g_part[NPART * 128];
__device__ float  g_bn  [128];
__device__ float g_wupf[7 * 2 * 2048];
__device__ float g_w1f [14 * 2048];
__device__ float g_w2f [7 * 2048];

__device__ __forceinline__ uint32_t pack_h2(float lo, float hi) {
    __half2 h = __floats2half2_rn(lo, hi);
    return *reinterpret_cast<uint32_t*>(&h);
}

#define MMA_F16(d, a0, a1, a2, a3, b0, b1)                                   \
    asm volatile("mma.sync.aligned.m16n8k16.row.col.f32.f16.f16.f32 "        \
        "{%0,%1,%2,%3}, {%4,%5,%6,%7}, {%8,%9}, {%0,%1,%2,%3};"              \
        : "+f"((d)[0]), "+f"((d)[1]), "+f"((d)[2]), "+f"((d)[3])             \
        : "r"(a0), "r"(a1), "r"(a2), "r"(a3), "r"(b0), "r"(b1))

#define CP_ASYNC16(dst_u32, src)                                             \
    asm volatile("cp.async.cg.shared.global [%0], [%1], 16;"                 \
                 :: "r"(dst_u32), "l"(src) : "memory")
#define CP_COMMIT()  asm volatile("cp.async.commit_group;" ::: "memory")
#define CP_WAIT(n)   asm volatile("cp.async.wait_group %0;" :: "n"(n) : "memory")

constexpr int AS_WORDS  = 128 * 36;            // 18,432 B per buffer
constexpr int SMEM_GEMM = 2 * AS_WORDS * 4;    // 36,864 B

// ---------------------------------------------------------------------------
__global__ void round_half(const float* __restrict__ src, __half* __restrict__ dst, long nquads)
{
    long i = (long)blockIdx.x * blockDim.x + threadIdx.x;
    if (i >= nquads) return;
    float4 v = ((const float4*)src)[i];
    ((uint2*)dst)[i] = make_uint2(pack_h2(v.x, v.y), pack_h2(v.z, v.w));
}

// ---------------------------------------------------------------------------
__global__ void prep_weights(const float* __restrict__ upW,
                             const float* __restrict__ W1,
                             const float* __restrict__ W2)
{
    int f = blockIdx.x * 256 + threadIdx.x;
    if (f >= 71680) return;
    int which, c, kc, t = 0;
    if (f < 28672)      { which = 0; t = f >> 12; int in_ = f & 4095; kc = in_ >> 11; c = in_ & 2047; }
    else if (f < 57344) { which = 1; int rel = f - 28672; kc = rel >> 11; c = rel & 2047; }
    else                { which = 2; int rel = f - 57344; kc = rel >> 11; c = rel & 2047; }
    int q    = c & 3;
    int lane = (c >> 2) & 31;
    int np   = (c >> 7) & 3;
    int ks   = (c >> 9) & 3;
    int nt   = np * 2 + (q >> 1);
    int bi   = q & 1;
    int n    = nt * 8 + (lane >> 2);
    int k0   = kc * 64 + ks * 16 + (lane & 3) * 2 + bi * 8;
    float s0, s1;
    if (which == 0)      { s0 = upW[k0 * 448 + t * 64 + n]; s1 = upW[(k0 + 1) * 448 + t * 64 + n]; }
    else if (which == 1) { s0 = W1[k0 * 64 + n];            s1 = W1[(k0 + 1) * 64 + n]; }
    else                 { s0 = W2[k0 * 64 + n];            s1 = W2[(k0 + 1) * 64 + n]; }
    uint32_t u = pack_h2(s0, s1);
    if (which == 0)      g_wupf[f]          = __uint_as_float(u);
    else if (which == 1) g_w1f[f - 28672]   = __uint_as_float(u);
    else                 g_w2f[f - 57344]   = __uint_as_float(u);
}

// ---------------------------------------------------------------------------
// 32-row warp-tile fp16 GEMM, (128,3), 2-buffer lookahead-1  [R11/R15 form]
// ---------------------------------------------------------------------------
#define MK_VARS()                                                             \
    extern __shared__ float sm[];                                             \
    const int tid = threadIdx.x, lane = tid & 31, warp = tid >> 5;            \
    const int frow = (warp << 5) + lane;                                      \
    uint32_t as_u32 = (uint32_t)__cvta_generic_to_shared(sm);                 \
    float acc[16][4];

#define MK_ACC_ZERO()                                                         \
    _Pragma("unroll") for (int i = 0; i < 16; i++)                            \
    _Pragma("unroll") for (int j = 0; j < 4; j++) acc[i][j] = 0.f;

#define MK_ISSUE(buf, rowptr)                                                 \
    {                                                                         \
        uint32_t d = as_u32 + ((buf) * AS_WORDS + frow * 36) * 4;             \
        const float4* s = (const float4*)(rowptr);                            \
        _Pragma("unroll")                                                     \
        for (int i = 0; i < 8; i++) CP_ASYNC16(d + i * 16, s + i);            \
        CP_COMMIT();                                                          \
    }

#define MK_COMPUTE(buf, bchunk)                                               \
    {                                                                         \
        const uint32_t* As = (const uint32_t*)sm + (buf) * AS_WORDS;          \
        const float4* bp = (const float4*)(bchunk) + lane;                    \
        const int r0 = (warp << 5) + (lane >> 2);                             \
        const int c2 = lane & 3;                                              \
        _Pragma("unroll")                                                     \
        for (int ks = 0; ks < 4; ks++) {                                      \
            float4 bv0 = __ldg(bp + (ks * 4 + 0) * 32);                       \
            float4 bv1 = __ldg(bp + (ks * 4 + 1) * 32);                       \
            float4 bv2 = __ldg(bp + (ks * 4 + 2) * 32);                       \
            float4 bv3 = __ldg(bp + (ks * 4 + 3) * 32);                       \
            uint32_t a0 = As[ r0       * 36 + ks * 8 + c2    ];               \
            uint32_t a1 = As[(r0 + 8)  * 36 + ks * 8 + c2    ];               \
            uint32_t a2 = As[ r0       * 36 + ks * 8 + c2 + 4];               \
            uint32_t a3 = As[(r0 + 8)  * 36 + ks * 8 + c2 + 4];               \
            uint32_t a4 = As[(r0 + 16) * 36 + ks * 8 + c2    ];               \
            uint32_t a5 = As[(r0 + 24) * 36 + ks * 8 + c2    ];               \
            uint32_t a6 = As[(r0 + 16) * 36 + ks * 8 + c2 + 4];               \
            uint32_t a7 = As[(r0 + 24) * 36 + ks * 8 + c2 + 4];               \
            MMA_F16(acc[0],  a0, a1, a2, a3, __float_as_uint(bv0.x), __float_as_uint(bv0.y)); \
            MMA_F16(acc[1],  a0, a1, a2, a3, __float_as_uint(bv0.z), __float_as_uint(bv0.w)); \
            MMA_F16(acc[8],  a4, a5, a6, a7, __float_as_uint(bv0.x), __float_as_uint(bv0.y)); \
            MMA_F16(acc[9],  a4, a5, a6, a7, __float_as_uint(bv0.z), __float_as_uint(bv0.w)); \
            MMA_F16(acc[2],  a0, a1, a2, a3, __float_as_uint(bv1.x), __float_as_uint(bv1.y)); \
            MMA_F16(acc[3],  a0, a1, a2, a3, __float_as_uint(bv1.z), __float_as_uint(bv1.w)); \
            MMA_F16(acc[10], a4, a5, a6, a7, __float_as_uint(bv1.x), __float_as_uint(bv1.y)); \
            MMA_F16(acc[11], a4, a5, a6, a7, __float_as_uint(bv1.z), __float_as_uint(bv1.w)); \
            MMA_F16(acc[4],  a0, a1, a2, a3, __float_as_uint(bv2.x), __float_as_uint(bv2.y)); \
            MMA_F16(acc[5],  a0, a1, a2, a3, __float_as_uint(bv2.z), __float_as_uint(bv2.w)); \
            MMA_F16(acc[12], a4, a5, a6, a7, __float_as_uint(bv2.x), __float_as_uint(bv2.y)); \
            MMA_F16(acc[13], a4, a5, a6, a7, __float_as_uint(bv2.z), __float_as_uint(bv2.w)); \
            MMA_F16(acc[6],  a0, a1, a2, a3, __float_as_uint(bv3.x), __float_as_uint(bv3.y)); \
            MMA_F16(acc[7],  a0, a1, a2, a3, __float_as_uint(bv3.z), __float_as_uint(bv3.w)); \
            MMA_F16(acc[14], a4, a5, a6, a7, __float_as_uint(bv3.x), __float_as_uint(bv3.y)); \
            MMA_F16(acc[15], a4, a5, a6, a7, __float_as_uint(bv3.z), __float_as_uint(bv3.w)); \
        }                                                                     \
    }

// fp16 epilogue: packed half2 stores
#define MK_EPILOGUE_H(dst, ldc, Mlim, biasp)                                  \
    {                                                                         \
        long mr = rowBase + (warp << 5) + (lane >> 2);                        \
        int  cb = (lane & 3) * 2;                                             \
        _Pragma("unroll")                                                     \
        for (int nt = 0; nt < 8; nt++) {                                      \
            float bx = (biasp)[nt * 8 + cb];                                  \
            float by = (biasp)[nt * 8 + cb + 1];                              \
            if (mr < (Mlim))                                                  \
                *(uint32_t*)((dst) + mr * (ldc) + nt * 8 + cb)                \
                    = pack_h2(acc[nt][0] + bx, acc[nt][1] + by);              \
            if (mr + 8 < (Mlim))                                              \
                *(uint32_t*)((dst) + (mr + 8) * (ldc) + nt * 8 + cb)          \
                    = pack_h2(acc[nt][2] + bx, acc[nt][3] + by);              \
            if (mr + 16 < (Mlim))                                             \
                *(uint32_t*)((dst) + (mr + 16) * (ldc) + nt * 8 + cb)         \
                    = pack_h2(acc[8 + nt][0] + bx, acc[8 + nt][1] + by);      \
            if (mr + 24 < (Mlim))                                             \
                *(uint32_t*)((dst) + (mr + 24) * (ldc) + nt * 8 + cb)         \
                    = pack_h2(acc[8 + nt][2] + bx, acc[8 + nt][3] + by);      \
        }                                                                     \
    }

#define MK_PIPELINE(NC, ROWPTR, WPTR)                                         \
    MK_ISSUE(0, ROWPTR(0));                                                   \
    _Pragma("unroll 1")                                                       \
    for (int kc = 0; kc < (NC); kc++) {                                       \
        if (kc + 1 < (NC)) { MK_ISSUE((kc + 1) & 1, ROWPTR(kc + 1)); CP_WAIT(1); } \
        else CP_WAIT(0);                                                      \
        __syncwarp();                                                         \
        MK_COMPUTE(kc & 1, (WPTR) + kc * 2048);                               \
    }

// ---------------------------------------------------------------------------
// GEMM 1: up-projection -> g_hh (fp16)
// ---------------------------------------------------------------------------
__global__ __launch_bounds__(128, 3) void gemm_up_mma(const float* __restrict__ bias)
{
    MK_VARS();
    const long rowBase = (long)blockIdx.x * 128;
    long fm = rowBase + frow; if (fm >= MUP) fm = MUP - 1;
    const __half* arow = g_x1h + fm * CIN;

    MK_ISSUE(0, arow);
    MK_ISSUE(1, arow + 64);
    CP_WAIT(0);
    __syncwarp();

    for (int t = 0; t < 7; t++) {
        MK_ACC_ZERO();
        MK_COMPUTE(0, g_wupf + (t * 2 + 0) * 2048);
        MK_COMPUTE(1, g_wupf + (t * 2 + 1) * 2048);
        MK_EPILOGUE_H(g_hh + t * 64, NUP, MUP, bias + t * 64);
    }
}

// ---------------------------------------------------------------------------
__global__ void build_xup(const int* __restrict__ topi, const int* __restrict__ downi)
{
    long idx = (long)blockIdx.x * blockDim.x + threadIdx.x;
    long total = (long)BB * NH * 16;
    if (idx >= total) return;
    long row = idx >> 4;
    int  q = (int)(idx & 15);
    int  b = (int)(row / NH);
    int  n = (int)(row - (long)b * NH);
    const __half* hb = g_hh + (size_t)b * NR * 7 * CO;
    uint2 r;
    if (n < NR) {
        int s = __ldg(topi + n);
        r = *(const uint2*)(hb + (long)s * CO + q * 4);
    } else {
        int m2 = n - NR;
        int s0 = __ldg(downi + 2 * m2);
        int s1 = __ldg(downi + 2 * m2 + 1);
        uint2 ua = *(const uint2*)(hb + (long)s0 * CO + q * 4);
        uint2 uc = *(const uint2*)(hb + (long)s1 * CO + q * 4);
        float2 a0 = __half22float2(*(__half2*)&ua.x);
        float2 a1 = __half22float2(*(__half2*)&ua.y);
        float2 c0 = __half22float2(*(__half2*)&uc.x);
        float2 c1 = __half22float2(*(__half2*)&uc.y);
        r.x = pack_h2(0.5f * (a0.x + c0.x), 0.5f * (a0.y + c0.y));
        r.y = pack_h2(0.5f * (a1.x + c1.x), 0.5f * (a1.y + c1.y));
    }
    *(uint2*)(g_xuph + row * CO + q * 4) = r;
}

// ---------------------------------------------------------------------------
// GEMM 2: conv1 -> g_yh (fp16 only)
// ---------------------------------------------------------------------------
__global__ __launch_bounds__(128, 3) void gemm_conv1_mma(const float* __restrict__ bias,
                                                         const int* __restrict__ neigh)
{
    MK_VARS();
    MK_ACC_ZERO();
    const long rowBase = (long)blockIdx.x * 128;
    long fm = rowBase + frow; if (fm >= MC) fm = MC - 1;
    const int  fb = (int)(fm / NH);
    const int  fn = (int)(fm - (long)fb * NH);
    const long bbase = (long)fb * NH;
    int nidx[7];
#pragma unroll
    for (int j = 0; j < 7; j++) nidx[j] = __ldg(neigh + (long)fn * 7 + j);

#define C1_ROW(kc) (((kc) & 1 ? g_x2h : g_xuph) + (bbase + nidx[(kc) >> 1]) * CO)
    MK_PIPELINE(14, C1_ROW, g_w1f);
#undef C1_ROW
    MK_EPILOGUE_H(g_yh, CO, MC, bias);
}

// ---------------------------------------------------------------------------
// GEMM 3: conv2 -> g_hh (fp16, reused buffer)
// ---------------------------------------------------------------------------
__global__ __launch_bounds__(128, 3) void gemm_conv2_mma(const float* __restrict__ bias,
                                                         const int* __restrict__ neigh)
{
    MK_VARS();
    MK_ACC_ZERO();
    const long rowBase = (long)blockIdx.x * 128;
    long fm = rowBase + frow; if (fm >= MC) fm = MC - 1;
    const int  fb = (int)(fm / NH);
    const int  fn = (int)(fm - (long)fb * NH);
    const long bbase = (long)fb * NH;
    int nidx[7];
#pragma unroll
    for (int j = 0; j < 7; j++) nidx[j] = __ldg(neigh + (long)fn * 7 + j);

#define C2_ROW(kc) (g_yh + (bbase + nidx[kc]) * CO)
    MK_PIPELINE(7, C2_ROW, g_w2f);
#undef C2_ROW
    MK_EPILOGUE_H(g_hh, CO, MC, bias);
}

// ---------------------------------------------------------------------------
// BN statistics from fp16 data
// ---------------------------------------------------------------------------
__global__ __launch_bounds__(256) void reduce_stats_h(const __half* __restrict__ data, long Mrows)
{
    __shared__ float4 sh_s [16][16];
    __shared__ float4 sh_ss[16][16];
    int q  = threadIdx.x & 15;
    int rg = threadIdx.x >> 4;
    float4 s  = make_float4(0.f, 0.f, 0.f, 0.f);
    float4 ss = make_float4(0.f, 0.f, 0.f, 0.f);
    for (long r = (long)blockIdx.x * 16 + rg; r < Mrows; r += (long)gridDim.x * 16) {
        uint2 u = *(const uint2*)(data + r * 64 + q * 4);
        float2 v0 = __half22float2(*(__half2*)&u.x);
        float2 v1 = __half22float2(*(__half2*)&u.y);
        s.x += v0.x; s.y += v0.y; s.z += v1.x; s.w += v1.y;
        ss.x = fmaf(v0.x, v0.x, ss.x); ss.y = fmaf(v0.y, v0.y, ss.y);
        ss.z = fmaf(v1.x, v1.x, ss.z); ss.w = fmaf(v1.y, v1.y, ss.w);
    }
    sh_s[rg][q] = s; sh_ss[rg][q] = ss;
    __syncthreads();
#pragma unroll
    for (int stride = 8; stride >= 1; stride >>= 1) {
        if (rg < stride) {
            float4 a = sh_s[rg][q], b = sh_s[rg + stride][q];
            a.x += b.x; a.y += b.y; a.z += b.z; a.w += b.w;
            sh_s[rg][q] = a;
            float4 c = sh_ss[rg][q], d = sh_ss[rg + stride][q];
            c.x += d.x; c.y += d.y; c.z += d.z; c.w += d.w;
            sh_ss[rg][q] = c;
        }
        __syncthreads();
    }
    if (rg == 0) {
        *(float4*)(g_part + blockIdx.x * 128 + q * 4)      = sh_s[0][q];
        *(float4*)(g_part + blockIdx.x * 128 + 64 + q * 4) = sh_ss[0][q];
    }
}

__global__ void bn_finalize(const float* __restrict__ gamma,
                            const float* __restrict__ beta, float invM)
{
    int c = threadIdx.x;
    float s = 0.f, ss = 0.f;
    for (int p = 0; p < NPART; p++) {
        s  += g_part[p * 128 + c];
        ss += g_part[p * 128 + 64 + c];
    }
    float mean = s * invM;
    float var  = fmaf(-mean, mean, ss * invM);
    float sc   = gamma[c] * rsqrtf(var + BN_EPS);
    g_bn[c]      = sc;
    g_bn[64 + c] = beta[c] - mean * sc;
}

// BN1 + lrelu in place on fp16 g_yh
__global__ void apply_bn1_inplace()
{
    long idx = (long)blockIdx.x * blockDim.x + threadIdx.x;
    if (idx >= MC * 16) return;
    int q = (int)(idx & 15);
    uint2 u = ((uint2*)g_yh)[idx];
    float2 v0 = __half22float2(*(__half2*)&u.x);
    float2 v1 = __half22float2(*(__half2*)&u.y);
    float4 sc = *(const float4*)&g_bn[q * 4];
    float4 sh = *(const float4*)&g_bn[64 + q * 4];
    float x = fmaf(v0.x, sc.x, sh.x); x = x >= 0.f ? x : LRELU_SLOPE * x;
    float y = fmaf(v0.y, sc.y, sh.y); y = y >= 0.f ? y : LRELU_SLOPE * y;
    float z = fmaf(v1.x, sc.z, sh.z); z = z >= 0.f ? z : LRELU_SLOPE * z;
    float w = fmaf(v1.y, sc.w, sh.w); w = w >= 0.f ? w : LRELU_SLOPE * w;
    ((uint2*)g_yh)[idx] = make_uint2(pack_h2(x, y), pack_h2(z, w));
}

// BN2 + lrelu: read fp16 g_hh, write fp32 out
__global__ void apply_bn2_out(float* __restrict__ out)
{
    long idx = (long)blockIdx.x * blockDim.x + threadIdx.x;
    if (idx >= MC * 16) return;
    int q = (int)(idx & 15);
    uint2 u = ((const uint2*)g_hh)[idx];
    float2 v0 = __half22float2(*(__half2*)&u.x);
    float2 v1 = __half22float2(*(__half2*)&u.y);
    float4 sc = *(const float4*)&g_bn[q * 4];
    float4 sh = *(const float4*)&g_bn[64 + q * 4];
    float x = fmaf(v0.x, sc.x, sh.x); x = x >= 0.f ? x : LRELU_SLOPE * x;
    float y = fmaf(v0.y, sc.y, sh.y); y = y >= 0.f ? y : LRELU_SLOPE * y;
    float z = fmaf(v1.x, sc.z, sh.z); z = z >= 0.f ? z : LRELU_SLOPE * z;
    float w = fmaf(v1.y, sc.w, sh.w); w = w >= 0.f ? w : LRELU_SLOPE * w;
    ((float4*)out)[idx] = make_float4(x, y, z, w);
}

// ---------------------------------------------------------------------------
extern "C" void kernel_launch(void* const* d_in, const int* in_sizes, int n_in,
                              void* d_out, int out_size)
{
    const float* x1    = (const float*)d_in[0];
    const float* x2    = (const float*)d_in[1];
    const int*   neigh = (const int*)  d_in[2];
    const int*   topi  = (const int*)  d_in[3];
    const int*   downi = (const int*)  d_in[4];
    const float* upW   = (const float*)d_in[5];
    const float* upb   = (const float*)d_in[6];
    const float* W1    = (const float*)d_in[7];
    const float* b1    = (const float*)d_in[8];
    const float* g1    = (const float*)d_in[9];
    const float* be1   = (const float*)d_in[10];
    const float* W2    = (const float*)d_in[11];
    const float* b2    = (const float*)d_in[12];
    const float* g2    = (const float*)d_in[13];
    const float* be2   = (const float*)d_in[14];
    float* out = (float*)d_out;

    cudaFuncSetAttribute(gemm_up_mma,    cudaFuncAttributeMaxDynamicSharedMemorySize, SMEM_GEMM);
    cudaFuncSetAttribute(gemm_conv1_mma, cudaFuncAttributeMaxDynamicSharedMemorySize, SMEM_GEMM);
    cudaFuncSetAttribute(gemm_conv2_mma, cudaFuncAttributeMaxDynamicSharedMemorySize, SMEM_GEMM);

    void *x1h = nullptr, *x2h = nullptr, *yhp = nullptr, *hhp = nullptr;
    cudaGetSymbolAddress(&x1h, g_x1h);
    cudaGetSymbolAddress(&x2h, g_x2h);
    cudaGetSymbolAddress(&yhp, g_yh);
    cudaGetSymbolAddress(&hhp, g_hh);

    const int blkUp = (int)((MUP + 127) / 128);
    const long quads   = (long)BB * NH * 16;
    const int ewBlocks = (int)((quads + 255) / 256);
    const int pwBlocks = (71680 + 255) / 256;
    const long q1 = MUP * CIN / 4, q2 = MC * CO / 4;

    prep_weights   <<<pwBlocks, 256>>>(upW, W1, W2);
    round_half     <<<(int)((q1 + 255) / 256), 256>>>(x1, (__half*)x1h, q1);
    round_half     <<<(int)((q2 + 255) / 256), 256>>>(x2, (__half*)x2h, q2);
    gemm_up_mma    <<<blkUp, 128, SMEM_GEMM>>>(upb);
    build_xup      <<<ewBlocks, 256>>>(topi, downi);
    gemm_conv1_mma <<<NCTA_C, 128, SMEM_GEMM>>>(b1, neigh);
    reduce_stats_h <<<NPART, 256>>>((const __half*)yhp, MC);
    bn_finalize    <<<1, 64>>>(g1, be1, 1.0f / (float)MC);
    apply_bn1_inplace<<<ewBlocks, 256>>>();
    gemm_conv2_mma <<<NCTA_C, 128, SMEM_GEMM>>>(b2, neigh);
    reduce_stats_h <<<NPART, 256>>>((const __half*)hhp, MC);
    bn_finalize    <<<1, 64>>>(g2, be2, 1.0f / (float)MC);
    apply_bn2_out  <<<ewBlocks, 256>>>(out);
}